// round 10
// baseline (speedup 1.0000x reference)
#include <cuda_runtime.h>
#include <cuda_bf16.h>

#define THREADS 512
#define NBLK 1024

// ---- smem byte offsets ----
#define XHI 0u            // X hi  [128][128] bf16, rowbytes 256, swizzled   (32KB)
#define XLO 32768u        // X lo                                            (32KB)
#define STGH 65536u       // stage hi [128][256] bf16, rowbytes 512, swz     (64KB)  T then V
#define STGL 131072u      // stage lo                                        (64KB)
#define SCOR 196608u      // scores/weights fp32 [256][34]                   (34816B)
#define SMEM_BYTES 231424u
#define SC_STRIDE 34

// precomputed B^T: rows n in [0,256): WV col n; n in [256,512): A_h rows (h=(n-256)/128, k2=(n-256)%128)
__device__ __align__(16) __nv_bfloat16 g_whi[512 * 128];
__device__ __align__(16) __nv_bfloat16 g_wlo[512 * 128];

// ================= prep kernel =================
__global__ void prep_w(const float* __restrict__ WQ, const float* __restrict__ WK,
                       const float* __restrict__ WV)
{
    const int n = blockIdx.x, k1 = threadIdx.x;
    __shared__ float wk[128];
    float val;
    if (n < 256) {
        val = WV[k1 * 256 + n];
    } else {
        const int h = (n - 256) >> 7, k2 = (n - 256) & 127;
        wk[k1] = WK[k2 * 256 + h * 128 + k1];
        __syncthreads();
        const float* wq = WQ + k1 * 256 + h * 128;
        float acc = 0.f;
#pragma unroll 8
        for (int e = 0; e < 128; ++e) acc = fmaf(wq[e], wk[e], acc);
        val = acc * 0.0625f;       // fold 1/sqrt(D*H)
    }
    __nv_bfloat16 hi = __float2bfloat16(val);
    g_whi[n * 128 + k1] = hi;
    g_wlo[n * 128 + k1] = __float2bfloat16(val - __bfloat162float(hi));
}

// ================= helpers =================
__device__ __forceinline__ unsigned swz(int r, unsigned off) {
    return off ^ (((unsigned)r & 7u) << 4);
}
__device__ __forceinline__ unsigned ldsm(const unsigned char* smp, unsigned base, int r, int c, int rb) {
    return *(const unsigned*)(smp + base + swz(r, (unsigned)(r * rb + c * 2)));
}
__device__ __forceinline__ void stsm(unsigned char* smp, unsigned base, int r, int c, int rb, unsigned v) {
    *(unsigned*)(smp + base + swz(r, (unsigned)(r * rb + c * 2))) = v;
}
__device__ __forceinline__ unsigned short lds16(const unsigned char* smp, unsigned base, int r, int c, int rb) {
    return *(const unsigned short*)(smp + base + swz(r, (unsigned)(r * rb + c * 2)));
}
__device__ __forceinline__ void split2(float a, float b, unsigned& hi, unsigned& lo) {
    __nv_bfloat16 ha = __float2bfloat16(a), hb = __float2bfloat16(b);
    float la = a - __bfloat162float(ha), lb = b - __bfloat162float(hb);
    __nv_bfloat16 lA = __float2bfloat16(la), lB = __float2bfloat16(lb);
    hi = ((unsigned)__bfloat16_as_ushort(hb) << 16) | (unsigned)__bfloat16_as_ushort(ha);
    lo = ((unsigned)__bfloat16_as_ushort(lB) << 16) | (unsigned)__bfloat16_as_ushort(lA);
}
__device__ __forceinline__ void mma_bf(float* d, const unsigned* a, const unsigned* b) {
    asm volatile(
        "mma.sync.aligned.m16n8k16.row.col.f32.bf16.bf16.f32 "
        "{%0,%1,%2,%3}, {%4,%5,%6,%7}, {%8,%9}, {%0,%1,%2,%3};\n"
        : "+f"(d[0]), "+f"(d[1]), "+f"(d[2]), "+f"(d[3])
        : "r"(a[0]), "r"(a[1]), "r"(a[2]), "r"(a[3]), "r"(b[0]), "r"(b[1]));
}

// projection GEMM: warp computes rows [mh*64, mh*64+64) x cols [nb, nb+32) of
// Y = X(128x128) * Wbig(128x512) slice; 3-pass compensated bf16; stage to STG.
// B rows in g_w start at nsel + nb.
__device__ __forceinline__ void proj_gemm(unsigned char* smp, int nsel, int nb, int mh,
                                          int grp, int q)
{
#pragma unroll
    for (int nc = 0; nc < 2; ++nc) {
        float D[2][4][4];
#pragma unroll
        for (int nt = 0; nt < 2; ++nt)
#pragma unroll
            for (int m = 0; m < 4; ++m)
#pragma unroll
                for (int e = 0; e < 4; ++e) D[nt][m][e] = 0.f;

        unsigned bh[2][2], bl[2][2];
#pragma unroll
        for (int nt = 0; nt < 2; ++nt) {
            const int n = nsel + nb + nc * 16 + nt * 8 + grp;
            const unsigned short* ph = (const unsigned short*)g_whi + n * 128 + 2 * q;
            const unsigned short* pl = (const unsigned short*)g_wlo + n * 128 + 2 * q;
            bh[nt][0] = *(const unsigned*)ph;  bh[nt][1] = *(const unsigned*)(ph + 8);
            bl[nt][0] = *(const unsigned*)pl;  bl[nt][1] = *(const unsigned*)(pl + 8);
        }

#pragma unroll
        for (int kt = 0; kt < 8; ++kt) {
            unsigned bh2[2][2], bl2[2][2];
            if (kt < 7) {
#pragma unroll
                for (int nt = 0; nt < 2; ++nt) {
                    const int n = nsel + nb + nc * 16 + nt * 8 + grp;
                    const unsigned short* ph = (const unsigned short*)g_whi + n * 128 + (kt + 1) * 16 + 2 * q;
                    const unsigned short* pl = (const unsigned short*)g_wlo + n * 128 + (kt + 1) * 16 + 2 * q;
                    bh2[nt][0] = *(const unsigned*)ph;  bh2[nt][1] = *(const unsigned*)(ph + 8);
                    bl2[nt][0] = *(const unsigned*)pl;  bl2[nt][1] = *(const unsigned*)(pl + 8);
                }
            }
            unsigned A[4][4];
            const int c0 = kt * 16 + 2 * q;
#pragma unroll
            for (int m = 0; m < 4; ++m) {
                const int r0 = mh * 64 + m * 16 + grp;
                A[m][0] = ldsm(smp, XHI, r0,     c0,     256);
                A[m][1] = ldsm(smp, XHI, r0 + 8, c0,     256);
                A[m][2] = ldsm(smp, XHI, r0,     c0 + 8, 256);
                A[m][3] = ldsm(smp, XHI, r0 + 8, c0 + 8, 256);
            }
#pragma unroll
            for (int nt = 0; nt < 2; ++nt)
#pragma unroll
                for (int m = 0; m < 4; ++m) mma_bf(D[nt][m], A[m], bh[nt]);
#pragma unroll
            for (int nt = 0; nt < 2; ++nt)
#pragma unroll
                for (int m = 0; m < 4; ++m) mma_bf(D[nt][m], A[m], bl[nt]);
#pragma unroll
            for (int m = 0; m < 4; ++m) {
                const int r0 = mh * 64 + m * 16 + grp;
                A[m][0] = ldsm(smp, XLO, r0,     c0,     256);
                A[m][1] = ldsm(smp, XLO, r0 + 8, c0,     256);
                A[m][2] = ldsm(smp, XLO, r0,     c0 + 8, 256);
                A[m][3] = ldsm(smp, XLO, r0 + 8, c0 + 8, 256);
            }
#pragma unroll
            for (int nt = 0; nt < 2; ++nt)
#pragma unroll
                for (int m = 0; m < 4; ++m) mma_bf(D[nt][m], A[m], bh[nt]);
#pragma unroll
            for (int nt = 0; nt < 2; ++nt)
#pragma unroll
                for (int u = 0; u < 2; ++u) {
                    bh[nt][u] = bh2[nt][u];
                    bl[nt][u] = bl2[nt][u];
                }
        }
        // stage (split hi/lo)
#pragma unroll
        for (int nt = 0; nt < 2; ++nt)
#pragma unroll
            for (int m = 0; m < 4; ++m) {
                const int r0 = mh * 64 + m * 16 + grp;
                const int c = nb + nc * 16 + nt * 8 + 2 * q;
                unsigned hi, lo;
                split2(D[nt][m][0], D[nt][m][1], hi, lo);
                stsm(smp, STGH, r0, c, 512, hi);
                stsm(smp, STGL, r0, c, 512, lo);
                split2(D[nt][m][2], D[nt][m][3], hi, lo);
                stsm(smp, STGH, r0 + 8, c, 512, hi);
                stsm(smp, STGL, r0 + 8, c, 512, lo);
            }
    }
}

// ================= main kernel: 1 CTA = 4 graphs, 16 warps =================
__global__ __launch_bounds__(THREADS, 1)
void attn_hmma(const float* __restrict__ x,
               float* __restrict__ out,      // [B*N, 128]
               float* __restrict__ weight)   // [B*N, 32, 2]
{
    extern __shared__ unsigned char smp[];
    const int t = threadIdx.x;
    const int w = t >> 5, lane = t & 31, grp = lane >> 2, q = lane & 3;

    // ---- load X, split hi/lo ----
    {
        const float2* xg = (const float2*)(x + (size_t)blockIdx.x * 16384);
#pragma unroll
        for (int it = 0; it < 16; ++it) {
            const int e2 = t + 512 * it;
            const float2 v = xg[e2];
            const int r = e2 >> 6, c = (e2 & 63) * 2;
            unsigned hi, lo;
            split2(v.x, v.y, hi, lo);
            stsm(smp, XHI, r, c, 256, hi);
            stsm(smp, XLO, r, c, 256, lo);
        }
    }
    __syncthreads();

    // ---- phase T: T = X * A_h^T (rows 256..511 of Wbig), staged [128][256] (h,k2) ----
    proj_gemm(smp, 256, (w >> 1) * 32, w & 1, grp, q);
    __syncthreads();

    // ---- phase S: warp (g, h, ih): 16 i-rows of S_gh[32x32] = T_gh * X_g^T ----
    {
        const int g = w >> 2, h = (w >> 1) & 1, ih = w & 1;
        float D[4][4];
#pragma unroll
        for (int nt = 0; nt < 4; ++nt)
#pragma unroll
            for (int e = 0; e < 4; ++e) D[nt][e] = 0.f;

#pragma unroll
        for (int kt = 0; kt < 8; ++kt) {
            const int K0 = h * 128 + kt * 16 + 2 * q;
            const int r0 = g * 32 + ih * 16 + grp;
            unsigned Ah[4], Al[4];
            Ah[0] = ldsm(smp, STGH, r0,     K0,     512);
            Ah[1] = ldsm(smp, STGH, r0 + 8, K0,     512);
            Ah[2] = ldsm(smp, STGH, r0,     K0 + 8, 512);
            Ah[3] = ldsm(smp, STGH, r0 + 8, K0 + 8, 512);
            Al[0] = ldsm(smp, STGL, r0,     K0,     512);
            Al[1] = ldsm(smp, STGL, r0 + 8, K0,     512);
            Al[2] = ldsm(smp, STGL, r0,     K0 + 8, 512);
            Al[3] = ldsm(smp, STGL, r0 + 8, K0 + 8, 512);
#pragma unroll
            for (int nt = 0; nt < 4; ++nt) {
                const int rn = g * 32 + nt * 8 + grp;
                const int ck = kt * 16 + 2 * q;
                unsigned Bh[2], Bl[2];
                Bh[0] = ldsm(smp, XHI, rn, ck,     256);
                Bh[1] = ldsm(smp, XHI, rn, ck + 8, 256);
                Bl[0] = ldsm(smp, XLO, rn, ck,     256);
                Bl[1] = ldsm(smp, XLO, rn, ck + 8, 256);
                mma_bf(D[nt], Ah, Bh);
                mma_bf(D[nt], Al, Bh);
                mma_bf(D[nt], Ah, Bl);
            }
        }
        // stage scores fp32
        float* sc = (float*)(smp + SCOR);
#pragma unroll
        for (int nt = 0; nt < 4; ++nt) {
            const int p = g * 64 + h * 32 + ih * 16 + grp;
            const int j = nt * 8 + 2 * q;
            float2 v0; v0.x = D[nt][0]; v0.y = D[nt][1];
            float2 v1; v1.x = D[nt][2]; v1.y = D[nt][3];
            *(float2*)&sc[p * SC_STRIDE + j] = v0;
            *(float2*)&sc[(p + 8) * SC_STRIDE + j] = v1;
        }
    }
    __syncthreads();

    // ---- sparsemax: thread t<256 owns problem p = t (g,h,i); in-place ----
    if (t < 256) {
        float* zrow = (float*)(smp + SCOR) + t * SC_STRIDE;
        float z[32], s[32];
#pragma unroll
        for (int j = 0; j < 32; ++j) { z[j] = zrow[j]; s[j] = z[j]; }
#pragma unroll
        for (int pass = 0; pass < 32; ++pass) {
            const int st = pass & 1;
#pragma unroll
            for (int idx = 0; idx < 31; ++idx) {
                if ((idx & 1) == st) {
                    const float a = s[idx], b = s[idx + 1];
                    s[idx] = fmaxf(a, b); s[idx + 1] = fminf(a, b);
                }
            }
        }
        float csum = 0.f, ssum = 0.f; int ksup = 0;
#pragma unroll
        for (int kk = 1; kk <= 32; ++kk) {
            const float zk = s[kk - 1];
            csum += zk;
            if (1.0f + (float)kk * zk > csum) { ksup += 1; ssum += zk; }
        }
        const float tau = (ssum - 1.0f) / (float)ksup;
#pragma unroll
        for (int j = 0; j < 32; ++j) zrow[j] = fmaxf(z[j] - tau, 0.f);
    }
    __syncthreads();

    // ---- weight -> gmem ----
    {
        float2* wg = (float2*)(weight + (size_t)blockIdx.x * 8192);
        const float* sc = (const float*)(smp + SCOR);
#pragma unroll
        for (int it = 0; it < 8; ++it) {
            const int idx = t + 512 * it;       // (gi, j)
            const int gi = idx >> 5, j = idx & 31;
            const int g = gi >> 5, i = gi & 31;
            float2 o;
            o.x = sc[(g * 64 + i) * SC_STRIDE + j];
            o.y = sc[(g * 64 + 32 + i) * SC_STRIDE + j];
            wg[idx] = o;
        }
    }

    // ---- phase V: V = X * WV (rows 0..255 of Wbig), staged into STG (T dead) ----
    proj_gemm(smp, 0, (w >> 1) * 32, w & 1, grp, q);
    __syncthreads();

    // ---- phase O: warp (g, dq): O_g[32 x 32] = (0.5*w) * V, both heads in K ----
    {
        const int g = w >> 2, dq = w & 3;
        const float* sc = (const float*)(smp + SCOR);
        float D[4][2][4];
#pragma unroll
        for (int n = 0; n < 4; ++n)
#pragma unroll
            for (int m = 0; m < 2; ++m)
#pragma unroll
                for (int e = 0; e < 4; ++e) D[n][m][e] = 0.f;

#pragma unroll
        for (int kt = 0; kt < 4; ++kt) {
            const int h = kt >> 1;
            const int jj = (kt * 16 + 2 * q) & 31;
            unsigned Ah[2][4], Al[2][4];
#pragma unroll
            for (int m = 0; m < 2; ++m) {
                const int p0 = g * 64 + h * 32 + m * 16 + grp;
                const float2 f0 = *(const float2*)&sc[p0 * SC_STRIDE + jj];
                const float2 f1 = *(const float2*)&sc[(p0 + 8) * SC_STRIDE + jj];
                const float2 f2 = *(const float2*)&sc[p0 * SC_STRIDE + jj + 8];
                const float2 f3 = *(const float2*)&sc[(p0 + 8) * SC_STRIDE + jj + 8];
                split2(0.5f * f0.x, 0.5f * f0.y, Ah[m][0], Al[m][0]);
                split2(0.5f * f1.x, 0.5f * f1.y, Ah[m][1], Al[m][1]);
                split2(0.5f * f2.x, 0.5f * f2.y, Ah[m][2], Al[m][2]);
                split2(0.5f * f3.x, 0.5f * f3.y, Ah[m][3], Al[m][3]);
            }
#pragma unroll
            for (int n = 0; n < 4; ++n) {
                const int cV = h * 128 + dq * 32 + n * 8 + grp;
                const int rb = g * 32 + jj;
                unsigned Bh[2], Bl[2];
                {
                    unsigned short a0 = lds16(smp, STGH, rb,     cV, 512);
                    unsigned short a1 = lds16(smp, STGH, rb + 1, cV, 512);
                    unsigned short a2 = lds16(smp, STGH, rb + 8, cV, 512);
                    unsigned short a3 = lds16(smp, STGH, rb + 9, cV, 512);
                    Bh[0] = (unsigned)a0 | ((unsigned)a1 << 16);
                    Bh[1] = (unsigned)a2 | ((unsigned)a3 << 16);
                    unsigned short b0 = lds16(smp, STGL, rb,     cV, 512);
                    unsigned short b1 = lds16(smp, STGL, rb + 1, cV, 512);
                    unsigned short b2 = lds16(smp, STGL, rb + 8, cV, 512);
                    unsigned short b3 = lds16(smp, STGL, rb + 9, cV, 512);
                    Bl[0] = (unsigned)b0 | ((unsigned)b1 << 16);
                    Bl[1] = (unsigned)b2 | ((unsigned)b3 << 16);
                }
#pragma unroll
                for (int m = 0; m < 2; ++m) {
                    mma_bf(D[n][m], Ah[m], Bh);
                    mma_bf(D[n][m], Al[m], Bh);
                    mma_bf(D[n][m], Ah[m], Bl);
                }
            }
        }
        // out write
#pragma unroll
        for (int n = 0; n < 4; ++n)
#pragma unroll
            for (int m = 0; m < 2; ++m) {
                const int i = m * 16 + grp;
                const int d = dq * 32 + n * 8 + 2 * q;
                const size_t row = ((size_t)blockIdx.x * 4 + g) * 32 + i;
                float2 v0; v0.x = D[n][m][0]; v0.y = D[n][m][1];
                float2 v1; v1.x = D[n][m][2]; v1.y = D[n][m][3];
                *(float2*)&out[row * 128 + d] = v0;
                *(float2*)&out[(row + 8) * 128 + d] = v1;
            }
    }
}

extern "C" void kernel_launch(void* const* d_in, const int* in_sizes, int n_in,
                              void* d_out, int out_size)
{
    (void)in_sizes; (void)n_in; (void)out_size;
    const float* x  = (const float*)d_in[0];
    const float* WK = (const float*)d_in[1];
    const float* WV = (const float*)d_in[2];
    const float* WQ = (const float*)d_in[3];

    float* out    = (float*)d_out;
    float* weight = out + (size_t)4096 * 32 * 128;

    prep_w<<<512, 128>>>(WQ, WK, WV);

    cudaFuncSetAttribute(attn_hmma, cudaFuncAttributeMaxDynamicSharedMemorySize, SMEM_BYTES);
    attn_hmma<<<NBLK, THREADS, SMEM_BYTES>>>(x, out, weight);
}

// round 11
// speedup vs baseline: 1.0699x; 1.0699x over previous
#include <cuda_runtime.h>
#include <cuda_bf16.h>

#define THREADS 512
#define NBLK 1024

// ---- smem byte offsets ----
#define XHI 0u            // X hi  [128][128] bf16, rowbytes 256, swizzled   (32KB)
#define XLO 32768u        // X lo                                            (32KB)
#define STGH 65536u       // stage hi [128][256] bf16, rowbytes 512, swz     (64KB)  T then V
#define STGL 131072u      // stage lo                                        (64KB)
#define SCOR 196608u      // scores/weights fp32 [256][34]                   (34816B)
#define SMEM_BYTES 231424u
#define SC_STRIDE 34

// precomputed B^T: rows n in [0,256): WV col n; n in [256,512): A_h rows (h=(n-256)/128, k2=(n-256)%128)
__device__ __align__(16) __nv_bfloat16 g_whi[512 * 128];
__device__ __align__(16) __nv_bfloat16 g_wlo[512 * 128];

// ================= prep kernel =================
__global__ void prep_w(const float* __restrict__ WQ, const float* __restrict__ WK,
                       const float* __restrict__ WV)
{
    const int n = blockIdx.x, k1 = threadIdx.x;
    __shared__ float wk[128];
    float val;
    if (n < 256) {
        val = WV[k1 * 256 + n];
    } else {
        const int h = (n - 256) >> 7, k2 = (n - 256) & 127;
        wk[k1] = WK[k2 * 256 + h * 128 + k1];
        __syncthreads();
        const float* wq = WQ + k1 * 256 + h * 128;
        float acc = 0.f;
#pragma unroll 8
        for (int e = 0; e < 128; ++e) acc = fmaf(wq[e], wk[e], acc);
        val = acc * 0.0625f;       // fold 1/sqrt(D*H)
    }
    __nv_bfloat16 hi = __float2bfloat16(val);
    g_whi[n * 128 + k1] = hi;
    g_wlo[n * 128 + k1] = __float2bfloat16(val - __bfloat162float(hi));
}

// ================= helpers =================
__device__ __forceinline__ unsigned swz(int r, unsigned off) {
    return off ^ (((unsigned)r & 7u) << 4);
}
__device__ __forceinline__ void stsm(unsigned char* smp, unsigned base, int r, int c, int rb, unsigned v) {
    *(unsigned*)(smp + base + swz(r, (unsigned)(r * rb + c * 2))) = v;
}
__device__ __forceinline__ void split2(float a, float b, unsigned& hi, unsigned& lo) {
    __nv_bfloat16 ha = __float2bfloat16(a), hb = __float2bfloat16(b);
    float la = a - __bfloat162float(ha), lb = b - __bfloat162float(hb);
    __nv_bfloat16 lA = __float2bfloat16(la), lB = __float2bfloat16(lb);
    hi = ((unsigned)__bfloat16_as_ushort(hb) << 16) | (unsigned)__bfloat16_as_ushort(ha);
    lo = ((unsigned)__bfloat16_as_ushort(lB) << 16) | (unsigned)__bfloat16_as_ushort(lA);
}
__device__ __forceinline__ void mma_bf(float* d, const unsigned* a, const unsigned* b) {
    asm volatile(
        "mma.sync.aligned.m16n8k16.row.col.f32.bf16.bf16.f32 "
        "{%0,%1,%2,%3}, {%4,%5,%6,%7}, {%8,%9}, {%0,%1,%2,%3};\n"
        : "+f"(d[0]), "+f"(d[1]), "+f"(d[2]), "+f"(d[3])
        : "r"(a[0]), "r"(a[1]), "r"(a[2]), "r"(a[3]), "r"(b[0]), "r"(b[1]));
}
__device__ __forceinline__ void ldmx4(unsigned a, unsigned& r0, unsigned& r1,
                                      unsigned& r2, unsigned& r3) {
    asm volatile("ldmatrix.sync.aligned.m8n8.x4.shared.b16 {%0,%1,%2,%3}, [%4];"
                 : "=r"(r0), "=r"(r1), "=r"(r2), "=r"(r3) : "r"(a));
}
__device__ __forceinline__ void ldmx4t(unsigned a, unsigned& r0, unsigned& r1,
                                       unsigned& r2, unsigned& r3) {
    asm volatile("ldmatrix.sync.aligned.m8n8.x4.trans.shared.b16 {%0,%1,%2,%3}, [%4];"
                 : "=r"(r0), "=r"(r1), "=r"(r2), "=r"(r3) : "r"(a));
}

// projection GEMM: warp computes rows [mh*64, mh*64+64) x cols [nb, nb+32) of
// Y = X(128x128) * Wbig(128x512) slice; 3-pass compensated bf16; stage to STG.
__device__ __forceinline__ void proj_gemm(unsigned char* smp, unsigned sb,
                                          int nsel, int nb, int mh,
                                          int lane, int grp, int q)
{
    const int mi = lane >> 3, lr = lane & 7;
    const unsigned xsw = (unsigned)lr << 4;
    // per-thread ldmatrix base offsets for A tiles (16x16): matrix mi covers
    // rows +((mi&1)*8), cols +((mi>>1)*8)
    unsigned offA[4];
#pragma unroll
    for (int m = 0; m < 4; ++m)
        offA[m] = (unsigned)((mh * 64 + m * 16 + (mi & 1) * 8 + lr) * 256 + (mi >> 1) * 16);

#pragma unroll
    for (int nc = 0; nc < 2; ++nc) {
        float D[2][4][4];
#pragma unroll
        for (int nt = 0; nt < 2; ++nt)
#pragma unroll
            for (int m = 0; m < 4; ++m)
#pragma unroll
                for (int e = 0; e < 4; ++e) D[nt][m][e] = 0.f;

        unsigned bh[2][2], bl[2][2];
#pragma unroll
        for (int nt = 0; nt < 2; ++nt) {
            const int n = nsel + nb + nc * 16 + nt * 8 + grp;
            const unsigned short* ph = (const unsigned short*)g_whi + n * 128 + 2 * q;
            const unsigned short* pl = (const unsigned short*)g_wlo + n * 128 + 2 * q;
            bh[nt][0] = *(const unsigned*)ph;  bh[nt][1] = *(const unsigned*)(ph + 8);
            bl[nt][0] = *(const unsigned*)pl;  bl[nt][1] = *(const unsigned*)(pl + 8);
        }

#pragma unroll
        for (int kt = 0; kt < 8; ++kt) {
            unsigned bh2[2][2], bl2[2][2];
            if (kt < 7) {
#pragma unroll
                for (int nt = 0; nt < 2; ++nt) {
                    const int n = nsel + nb + nc * 16 + nt * 8 + grp;
                    const unsigned short* ph = (const unsigned short*)g_whi + n * 128 + (kt + 1) * 16 + 2 * q;
                    const unsigned short* pl = (const unsigned short*)g_wlo + n * 128 + (kt + 1) * 16 + 2 * q;
                    bh2[nt][0] = *(const unsigned*)ph;  bh2[nt][1] = *(const unsigned*)(ph + 8);
                    bl2[nt][0] = *(const unsigned*)pl;  bl2[nt][1] = *(const unsigned*)(pl + 8);
                }
            }
            const unsigned ck = (unsigned)(kt * 32);
            unsigned A[4][4];
#pragma unroll
            for (int m = 0; m < 4; ++m)
                ldmx4(sb + XHI + ((offA[m] + ck) ^ xsw), A[m][0], A[m][1], A[m][2], A[m][3]);
#pragma unroll
            for (int nt = 0; nt < 2; ++nt)
#pragma unroll
                for (int m = 0; m < 4; ++m) mma_bf(D[nt][m], A[m], bh[nt]);
#pragma unroll
            for (int nt = 0; nt < 2; ++nt)
#pragma unroll
                for (int m = 0; m < 4; ++m) mma_bf(D[nt][m], A[m], bl[nt]);
#pragma unroll
            for (int m = 0; m < 4; ++m)
                ldmx4(sb + XLO + ((offA[m] + ck) ^ xsw), A[m][0], A[m][1], A[m][2], A[m][3]);
#pragma unroll
            for (int nt = 0; nt < 2; ++nt)
#pragma unroll
                for (int m = 0; m < 4; ++m) mma_bf(D[nt][m], A[m], bh[nt]);
#pragma unroll
            for (int nt = 0; nt < 2; ++nt)
#pragma unroll
                for (int u = 0; u < 2; ++u) {
                    bh[nt][u] = bh2[nt][u];
                    bl[nt][u] = bl2[nt][u];
                }
        }
        // stage (split hi/lo)
#pragma unroll
        for (int nt = 0; nt < 2; ++nt)
#pragma unroll
            for (int m = 0; m < 4; ++m) {
                const int r0 = mh * 64 + m * 16 + grp;
                const int c = nb + nc * 16 + nt * 8 + 2 * q;
                unsigned hi, lo;
                split2(D[nt][m][0], D[nt][m][1], hi, lo);
                stsm(smp, STGH, r0, c, 512, hi);
                stsm(smp, STGL, r0, c, 512, lo);
                split2(D[nt][m][2], D[nt][m][3], hi, lo);
                stsm(smp, STGH, r0 + 8, c, 512, hi);
                stsm(smp, STGL, r0 + 8, c, 512, lo);
            }
    }
}

// ================= main kernel: 1 CTA = 4 graphs, 16 warps =================
__global__ __launch_bounds__(THREADS, 1)
void attn_hmma(const float* __restrict__ x,
               float* __restrict__ out,      // [B*N, 128]
               float* __restrict__ weight)   // [B*N, 32, 2]
{
    extern __shared__ unsigned char smp[];
    const unsigned sb = (unsigned)__cvta_generic_to_shared(smp);
    const int t = threadIdx.x;
    const int w = t >> 5, lane = t & 31, grp = lane >> 2, q = lane & 3;
    const int mi = lane >> 3, lr = lane & 7;
    const unsigned xsw = (unsigned)lr << 4;

    // ---- load X, split hi/lo ----
    {
        const float2* xg = (const float2*)(x + (size_t)blockIdx.x * 16384);
#pragma unroll
        for (int it = 0; it < 16; ++it) {
            const int e2 = t + 512 * it;
            const float2 v = xg[e2];
            const int r = e2 >> 6, c = (e2 & 63) * 2;
            unsigned hi, lo;
            split2(v.x, v.y, hi, lo);
            stsm(smp, XHI, r, c, 256, hi);
            stsm(smp, XLO, r, c, 256, lo);
        }
    }
    __syncthreads();

    // ---- phase T: T = X * A_h^T (rows 256..511 of Wbig), staged [128][256] (h,k2) ----
    proj_gemm(smp, sb, 256, (w >> 1) * 32, w & 1, lane, grp, q);
    __syncthreads();

    // ---- phase S: warp (g, h, ih): 16 i-rows of S_gh[32x32] = T_gh * X_g^T ----
    {
        const int g = w >> 2, h = (w >> 1) & 1, ih = w & 1;
        float D[4][4];
#pragma unroll
        for (int nt = 0; nt < 4; ++nt)
#pragma unroll
            for (int e = 0; e < 4; ++e) D[nt][e] = 0.f;

        // A from STG: 16x16 tile, rows g*32+ih*16, cols h*128 + k
        const unsigned offSA = (unsigned)((g * 32 + ih * 16 + (mi & 1) * 8 + lr) * 512
                                          + (mi >> 1) * 16 + h * 256);
        // B from X: matrices (nt, kchunk); first x4 covers nt0/nt1, second nt2/nt3
        const unsigned offSB = (unsigned)((g * 32 + (mi >> 1) * 8 + lr) * 256 + (mi & 1) * 16);

#pragma unroll
        for (int kt = 0; kt < 8; ++kt) {
            const unsigned ck = (unsigned)(kt * 32);
            unsigned Ah[4], Al[4];
            ldmx4(sb + STGH + ((offSA + ck) ^ xsw), Ah[0], Ah[1], Ah[2], Ah[3]);
            ldmx4(sb + STGL + ((offSA + ck) ^ xsw), Al[0], Al[1], Al[2], Al[3]);
            unsigned Bh[4][2], Bl[4][2];
            ldmx4(sb + XHI + ((offSB + ck) ^ xsw),        Bh[0][0], Bh[0][1], Bh[1][0], Bh[1][1]);
            ldmx4(sb + XHI + ((offSB + 4096 + ck) ^ xsw), Bh[2][0], Bh[2][1], Bh[3][0], Bh[3][1]);
            ldmx4(sb + XLO + ((offSB + ck) ^ xsw),        Bl[0][0], Bl[0][1], Bl[1][0], Bl[1][1]);
            ldmx4(sb + XLO + ((offSB + 4096 + ck) ^ xsw), Bl[2][0], Bl[2][1], Bl[3][0], Bl[3][1]);
#pragma unroll
            for (int nt = 0; nt < 4; ++nt) {
                mma_bf(D[nt], Ah, Bh[nt]);
                mma_bf(D[nt], Al, Bh[nt]);
                mma_bf(D[nt], Ah, Bl[nt]);
            }
        }
        // stage scores fp32
        float* sc = (float*)(smp + SCOR);
#pragma unroll
        for (int nt = 0; nt < 4; ++nt) {
            const int p = g * 64 + h * 32 + ih * 16 + grp;
            const int j = nt * 8 + 2 * q;
            float2 v0; v0.x = D[nt][0]; v0.y = D[nt][1];
            float2 v1; v1.x = D[nt][2]; v1.y = D[nt][3];
            *(float2*)&sc[p * SC_STRIDE + j] = v0;
            *(float2*)&sc[(p + 8) * SC_STRIDE + j] = v1;
        }
    }
    __syncthreads();

    // ---- sparsemax: thread t<256 owns problem p = t (g,h,i); in-place ----
    if (t < 256) {
        float* zrow = (float*)(smp + SCOR) + t * SC_STRIDE;
        float z[32], s[32];
#pragma unroll
        for (int j = 0; j < 32; ++j) { z[j] = zrow[j]; s[j] = z[j]; }
#pragma unroll
        for (int pass = 0; pass < 32; ++pass) {
            const int st = pass & 1;
#pragma unroll
            for (int idx = 0; idx < 31; ++idx) {
                if ((idx & 1) == st) {
                    const float a = s[idx], b = s[idx + 1];
                    s[idx] = fmaxf(a, b); s[idx + 1] = fminf(a, b);
                }
            }
        }
        float csum = 0.f, ssum = 0.f; int ksup = 0;
#pragma unroll
        for (int kk = 1; kk <= 32; ++kk) {
            const float zk = s[kk - 1];
            csum += zk;
            if (1.0f + (float)kk * zk > csum) { ksup += 1; ssum += zk; }
        }
        const float tau = (ssum - 1.0f) / (float)ksup;
#pragma unroll
        for (int j = 0; j < 32; ++j) zrow[j] = fmaxf(z[j] - tau, 0.f);
    }
    __syncthreads();

    // ---- weight -> gmem ----
    {
        float2* wg = (float2*)(weight + (size_t)blockIdx.x * 8192);
        const float* sc = (const float*)(smp + SCOR);
#pragma unroll
        for (int it = 0; it < 8; ++it) {
            const int idx = t + 512 * it;       // (gi, j)
            const int gi = idx >> 5, j = idx & 31;
            const int g = gi >> 5, i = gi & 31;
            float2 o;
            o.x = sc[(g * 64 + i) * SC_STRIDE + j];
            o.y = sc[(g * 64 + 32 + i) * SC_STRIDE + j];
            wg[idx] = o;
        }
    }

    // ---- phase V: V = X * WV (rows 0..255 of Wbig), staged into STG (T dead) ----
    proj_gemm(smp, sb, 0, (w >> 1) * 32, w & 1, lane, grp, q);
    __syncthreads();

    // ---- phase O: warp (g, dq): O_g[32 x 32] = (0.5*w) * V, both heads in K ----
    {
        const int g = w >> 2, dq = w & 3;
        const float* sc = (const float*)(smp + SCOR);
        float D[4][2][4];
#pragma unroll
        for (int n = 0; n < 4; ++n)
#pragma unroll
            for (int m = 0; m < 2; ++m)
#pragma unroll
                for (int e = 0; e < 4; ++e) D[n][m][e] = 0.f;

        // B (V^T gather) via ldmatrix.trans: matrices (nt, j-octet)
        const unsigned offOB = (unsigned)((g * 32 + (mi & 1) * 8 + lr) * 512
                                          + (mi >> 1) * 16 + dq * 64);

#pragma unroll
        for (int kt = 0; kt < 4; ++kt) {
            const int h = kt >> 1;
            const int jj = (kt * 16 + 2 * q) & 31;
            unsigned Ah[2][4], Al[2][4];
#pragma unroll
            for (int m = 0; m < 2; ++m) {
                const int p0 = g * 64 + h * 32 + m * 16 + grp;
                const float2 f0 = *(const float2*)&sc[p0 * SC_STRIDE + jj];
                const float2 f1 = *(const float2*)&sc[(p0 + 8) * SC_STRIDE + jj];
                const float2 f2 = *(const float2*)&sc[p0 * SC_STRIDE + jj + 8];
                const float2 f3 = *(const float2*)&sc[(p0 + 8) * SC_STRIDE + jj + 8];
                split2(0.5f * f0.x, 0.5f * f0.y, Ah[m][0], Al[m][0]);
                split2(0.5f * f1.x, 0.5f * f1.y, Ah[m][1], Al[m][1]);
                split2(0.5f * f2.x, 0.5f * f2.y, Ah[m][2], Al[m][2]);
                split2(0.5f * f3.x, 0.5f * f3.y, Ah[m][3], Al[m][3]);
            }
            const unsigned koff = (unsigned)((kt & 1) * 8192 + (kt >> 1) * 256);
            unsigned Bh[4][2], Bl[4][2];
            ldmx4t(sb + STGH + ((offOB + koff) ^ xsw),      Bh[0][0], Bh[0][1], Bh[1][0], Bh[1][1]);
            ldmx4t(sb + STGH + ((offOB + koff + 32) ^ xsw), Bh[2][0], Bh[2][1], Bh[3][0], Bh[3][1]);
            ldmx4t(sb + STGL + ((offOB + koff) ^ xsw),      Bl[0][0], Bl[0][1], Bl[1][0], Bl[1][1]);
            ldmx4t(sb + STGL + ((offOB + koff + 32) ^ xsw), Bl[2][0], Bl[2][1], Bl[3][0], Bl[3][1]);
#pragma unroll
            for (int n = 0; n < 4; ++n)
#pragma unroll
                for (int m = 0; m < 2; ++m) {
                    mma_bf(D[n][m], Ah[m], Bh[n]);
                    mma_bf(D[n][m], Al[m], Bh[n]);
                    mma_bf(D[n][m], Ah[m], Bl[n]);
                }
        }
        // out write
#pragma unroll
        for (int n = 0; n < 4; ++n)
#pragma unroll
            for (int m = 0; m < 2; ++m) {
                const int i = m * 16 + grp;
                const int d = dq * 32 + n * 8 + 2 * q;
                const size_t row = ((size_t)blockIdx.x * 4 + g) * 32 + i;
                float2 v0; v0.x = D[n][m][0]; v0.y = D[n][m][1];
                float2 v1; v1.x = D[n][m][2]; v1.y = D[n][m][3];
                *(float2*)&out[row * 128 + d] = v0;
                *(float2*)&out[(row + 8) * 128 + d] = v1;
            }
    }
}

extern "C" void kernel_launch(void* const* d_in, const int* in_sizes, int n_in,
                              void* d_out, int out_size)
{
    (void)in_sizes; (void)n_in; (void)out_size;
    const float* x  = (const float*)d_in[0];
    const float* WK = (const float*)d_in[1];
    const float* WV = (const float*)d_in[2];
    const float* WQ = (const float*)d_in[3];

    float* out    = (float*)d_out;
    float* weight = out + (size_t)4096 * 32 * 128;

    prep_w<<<512, 128>>>(WQ, WK, WV);

    cudaFuncSetAttribute(attn_hmma, cudaFuncAttributeMaxDynamicSharedMemorySize, SMEM_BYTES);
    attn_hmma<<<NBLK, THREADS, SMEM_BYTES>>>(x, out, weight);
}

// round 13
// speedup vs baseline: 1.1322x; 1.0582x over previous
#include <cuda_runtime.h>
#include <cuda_bf16.h>

#define THREADS 512
#define NBLK 1024

// ---- smem byte offsets ----
#define XHI 0u            // X hi  [128][128] bf16, rowbytes 256, swizzled   (32KB)
#define XLO 32768u        // X lo                                            (32KB)
#define STGH 65536u       // stage hi [128][256] bf16, rowbytes 512, swz     (64KB)  T then V
#define STGL 131072u      // stage lo                                        (64KB)
#define SCOR 196608u      // scores/weights fp32 [256][34]                   (34816B)
#define SMEM_BYTES 231424u
#define SC_STRIDE 34

// precomputed B^T: rows n in [0,256): WV col n; n in [256,512): A_h rows (h=(n-256)/128, k2=(n-256)%128)
__device__ __align__(16) __nv_bfloat16 g_whi[512 * 128];
__device__ __align__(16) __nv_bfloat16 g_wlo[512 * 128];

// ================= prep kernel =================
__global__ void prep_w(const float* __restrict__ WQ, const float* __restrict__ WK,
                       const float* __restrict__ WV)
{
    const int n = blockIdx.x, k1 = threadIdx.x;
    __shared__ float wk[128];
    float val;
    if (n < 256) {
        val = WV[k1 * 256 + n];
    } else {
        const int h = (n - 256) >> 7, k2 = (n - 256) & 127;
        wk[k1] = WK[k2 * 256 + h * 128 + k1];
        __syncthreads();
        const float* wq = WQ + k1 * 256 + h * 128;
        float acc = 0.f;
#pragma unroll 8
        for (int e = 0; e < 128; ++e) acc = fmaf(wq[e], wk[e], acc);
        val = acc * 0.0625f;       // fold 1/sqrt(D*H)
    }
    __nv_bfloat16 hi = __float2bfloat16(val);
    g_whi[n * 128 + k1] = hi;
    g_wlo[n * 128 + k1] = __float2bfloat16(val - __bfloat162float(hi));
}

// ================= helpers =================
__device__ __forceinline__ unsigned swz(int r, unsigned off) {
    return off ^ (((unsigned)r & 7u) << 4);
}
__device__ __forceinline__ void stsm(unsigned char* smp, unsigned base, int r, int c, int rb, unsigned v) {
    *(unsigned*)(smp + base + swz(r, (unsigned)(r * rb + c * 2))) = v;
}
__device__ __forceinline__ void split2(float a, float b, unsigned& hi, unsigned& lo) {
    __nv_bfloat16 ha = __float2bfloat16(a), hb = __float2bfloat16(b);
    float la = a - __bfloat162float(ha), lb = b - __bfloat162float(hb);
    __nv_bfloat16 lA = __float2bfloat16(la), lB = __float2bfloat16(lb);
    hi = ((unsigned)__bfloat16_as_ushort(hb) << 16) | (unsigned)__bfloat16_as_ushort(ha);
    lo = ((unsigned)__bfloat16_as_ushort(lB) << 16) | (unsigned)__bfloat16_as_ushort(lA);
}
__device__ __forceinline__ void mma_bf(float* d, const unsigned* a, const unsigned* b) {
    asm volatile(
        "mma.sync.aligned.m16n8k16.row.col.f32.bf16.bf16.f32 "
        "{%0,%1,%2,%3}, {%4,%5,%6,%7}, {%8,%9}, {%0,%1,%2,%3};\n"
        : "+f"(d[0]), "+f"(d[1]), "+f"(d[2]), "+f"(d[3])
        : "r"(a[0]), "r"(a[1]), "r"(a[2]), "r"(a[3]), "r"(b[0]), "r"(b[1]));
}
__device__ __forceinline__ void ldmx4(unsigned a, unsigned& r0, unsigned& r1,
                                      unsigned& r2, unsigned& r3) {
    asm volatile("ldmatrix.sync.aligned.m8n8.x4.shared.b16 {%0,%1,%2,%3}, [%4];"
                 : "=r"(r0), "=r"(r1), "=r"(r2), "=r"(r3) : "r"(a));
}
__device__ __forceinline__ void ldmx4t(unsigned a, unsigned& r0, unsigned& r1,
                                       unsigned& r2, unsigned& r3) {
    asm volatile("ldmatrix.sync.aligned.m8n8.x4.trans.shared.b16 {%0,%1,%2,%3}, [%4];"
                 : "=r"(r0), "=r"(r1), "=r"(r2), "=r"(r3) : "r"(a));
}

// projection GEMM: warp computes rows [mh*64, mh*64+64) x cols [nb, nb+32) of
// Y = X(128x128) * Wbig(128x512) slice; 3-pass compensated bf16; stage to STG.
// A (X) fragments are loaded ONCE per kt and reused across all 4 n-octets.
__device__ __forceinline__ void proj_gemm(unsigned char* smp, unsigned sb,
                                          int nsel, int nb, int mh,
                                          int lane, int grp, int q)
{
    const int mi = lane >> 3, lr = lane & 7;
    const unsigned xsw = (unsigned)lr << 4;
    unsigned offA[4];
#pragma unroll
    for (int m = 0; m < 4; ++m)
        offA[m] = (unsigned)((mh * 64 + m * 16 + (mi & 1) * 8 + lr) * 256 + (mi >> 1) * 16);

    float D[4][4][4];   // [p = nc*2+nt][m][4]
#pragma unroll
    for (int p = 0; p < 4; ++p)
#pragma unroll
        for (int m = 0; m < 4; ++m)
#pragma unroll
            for (int e = 0; e < 4; ++e) D[p][m][e] = 0.f;

    const unsigned short* wh = (const unsigned short*)g_whi + (nsel + nb + grp) * 128 + 2 * q;
    const unsigned short* wl = (const unsigned short*)g_wlo + (nsel + nb + grp) * 128 + 2 * q;

#pragma unroll
    for (int kt = 0; kt < 8; ++kt) {
        // B fragments for all 4 n-octets of this kt (hi + lo)
        unsigned bh[4][2], bl[4][2];
#pragma unroll
        for (int p = 0; p < 4; ++p) {
            const int off = ((p >> 1) * 16 + (p & 1) * 8) * 128 + kt * 16;
            bh[p][0] = *(const unsigned*)(wh + off);
            bh[p][1] = *(const unsigned*)(wh + off + 8);
            bl[p][0] = *(const unsigned*)(wl + off);
            bl[p][1] = *(const unsigned*)(wl + off + 8);
        }
        const unsigned ck = (unsigned)(kt * 32);
        unsigned A[4][4];
#pragma unroll
        for (int m = 0; m < 4; ++m)
            ldmx4(sb + XHI + ((offA[m] + ck) ^ xsw), A[m][0], A[m][1], A[m][2], A[m][3]);
#pragma unroll
        for (int p = 0; p < 4; ++p)
#pragma unroll
            for (int m = 0; m < 4; ++m) mma_bf(D[p][m], A[m], bh[p]);
#pragma unroll
        for (int p = 0; p < 4; ++p)
#pragma unroll
            for (int m = 0; m < 4; ++m) mma_bf(D[p][m], A[m], bl[p]);
        // reload A with XLO in the same registers
#pragma unroll
        for (int m = 0; m < 4; ++m)
            ldmx4(sb + XLO + ((offA[m] + ck) ^ xsw), A[m][0], A[m][1], A[m][2], A[m][3]);
#pragma unroll
        for (int p = 0; p < 4; ++p)
#pragma unroll
            for (int m = 0; m < 4; ++m) mma_bf(D[p][m], A[m], bh[p]);
    }

    // stage (split hi/lo)
#pragma unroll
    for (int p = 0; p < 4; ++p)
#pragma unroll
        for (int m = 0; m < 4; ++m) {
            const int r0 = mh * 64 + m * 16 + grp;
            const int c = nb + (p >> 1) * 16 + (p & 1) * 8 + 2 * q;
            unsigned hi, lo;
            split2(D[p][m][0], D[p][m][1], hi, lo);
            stsm(smp, STGH, r0, c, 512, hi);
            stsm(smp, STGL, r0, c, 512, lo);
            split2(D[p][m][2], D[p][m][3], hi, lo);
            stsm(smp, STGH, r0 + 8, c, 512, hi);
            stsm(smp, STGL, r0 + 8, c, 512, lo);
        }
}

// ================= main kernel: 1 CTA = 4 graphs, 16 warps =================
__global__ __launch_bounds__(THREADS, 1)
void attn_hmma(const float* __restrict__ x,
               float* __restrict__ out,      // [B*N, 128]
               float* __restrict__ weight)   // [B*N, 32, 2]
{
    extern __shared__ unsigned char smp[];
    const unsigned sb = (unsigned)__cvta_generic_to_shared(smp);
    const int t = threadIdx.x;
    const int w = t >> 5, lane = t & 31, grp = lane >> 2, q = lane & 3;
    const int mi = lane >> 3, lr = lane & 7;
    const unsigned xsw = (unsigned)lr << 4;

    // ---- load X, split hi/lo ----
    {
        const float2* xg = (const float2*)(x + (size_t)blockIdx.x * 16384);
#pragma unroll
        for (int it = 0; it < 16; ++it) {
            const int e2 = t + 512 * it;
            const float2 v = xg[e2];
            const int r = e2 >> 6, c = (e2 & 63) * 2;
            unsigned hi, lo;
            split2(v.x, v.y, hi, lo);
            stsm(smp, XHI, r, c, 256, hi);
            stsm(smp, XLO, r, c, 256, lo);
        }
    }
    __syncthreads();

    // ---- phase T: T = X * A_h^T (rows 256..511 of Wbig), staged [128][256] (h,k2) ----
    proj_gemm(smp, sb, 256, (w >> 1) * 32, w & 1, lane, grp, q);
    __syncthreads();

    // ---- phase S: warp (g, h, ih): 16 i-rows of S_gh[32x32] = T_gh * X_g^T ----
    {
        const int g = w >> 2, h = (w >> 1) & 1, ih = w & 1;
        float D[4][4];
#pragma unroll
        for (int nt = 0; nt < 4; ++nt)
#pragma unroll
            for (int e = 0; e < 4; ++e) D[nt][e] = 0.f;

        // A from STG: 16x16 tile, rows g*32+ih*16, cols h*128 + k
        const unsigned offSA = (unsigned)((g * 32 + ih * 16 + (mi & 1) * 8 + lr) * 512
                                          + (mi >> 1) * 16 + h * 256);
        // B from X: matrices (nt, kchunk); first x4 covers nt0/nt1, second nt2/nt3
        const unsigned offSB = (unsigned)((g * 32 + (mi >> 1) * 8 + lr) * 256 + (mi & 1) * 16);

#pragma unroll
        for (int kt = 0; kt < 8; ++kt) {
            const unsigned ck = (unsigned)(kt * 32);
            unsigned Ah[4], Al[4];
            ldmx4(sb + STGH + ((offSA + ck) ^ xsw), Ah[0], Ah[1], Ah[2], Ah[3]);
            ldmx4(sb + STGL + ((offSA + ck) ^ xsw), Al[0], Al[1], Al[2], Al[3]);
            unsigned Bh[4][2], Bl[4][2];
            ldmx4(sb + XHI + ((offSB + ck) ^ xsw),        Bh[0][0], Bh[0][1], Bh[1][0], Bh[1][1]);
            ldmx4(sb + XHI + ((offSB + 4096 + ck) ^ xsw), Bh[2][0], Bh[2][1], Bh[3][0], Bh[3][1]);
            ldmx4(sb + XLO + ((offSB + ck) ^ xsw),        Bl[0][0], Bl[0][1], Bl[1][0], Bl[1][1]);
            ldmx4(sb + XLO + ((offSB + 4096 + ck) ^ xsw), Bl[2][0], Bl[2][1], Bl[3][0], Bl[3][1]);
#pragma unroll
            for (int nt = 0; nt < 4; ++nt) {
                mma_bf(D[nt], Ah, Bh[nt]);
                mma_bf(D[nt], Al, Bh[nt]);
                mma_bf(D[nt], Ah, Bl[nt]);
            }
        }
        // stage scores fp32
        float* sc = (float*)(smp + SCOR);
#pragma unroll
        for (int nt = 0; nt < 4; ++nt) {
            const int p = g * 64 + h * 32 + ih * 16 + grp;
            const int j = nt * 8 + 2 * q;
            float2 v0; v0.x = D[nt][0]; v0.y = D[nt][1];
            float2 v1; v1.x = D[nt][2]; v1.y = D[nt][3];
            *(float2*)&sc[p * SC_STRIDE + j] = v0;
            *(float2*)&sc[(p + 8) * SC_STRIDE + j] = v1;
        }
    }
    __syncthreads();

    // ---- sparsemax: thread t<256 owns problem p = t (g,h,i); in-place ----
    if (t < 256) {
        float* zrow = (float*)(smp + SCOR) + t * SC_STRIDE;
        float z[32], s[32];
#pragma unroll
        for (int j = 0; j < 32; ++j) { z[j] = zrow[j]; s[j] = z[j]; }
#pragma unroll
        for (int pass = 0; pass < 32; ++pass) {
            const int st = pass & 1;
#pragma unroll
            for (int idx = 0; idx < 31; ++idx) {
                if ((idx & 1) == st) {
                    const float a = s[idx], b = s[idx + 1];
                    s[idx] = fmaxf(a, b); s[idx + 1] = fminf(a, b);
                }
            }
        }
        float csum = 0.f, ssum = 0.f; int ksup = 0;
#pragma unroll
        for (int kk = 1; kk <= 32; ++kk) {
            const float zk = s[kk - 1];
            csum += zk;
            if (1.0f + (float)kk * zk > csum) { ksup += 1; ssum += zk; }
        }
        const float tau = (ssum - 1.0f) / (float)ksup;
#pragma unroll
        for (int j = 0; j < 32; ++j) zrow[j] = fmaxf(z[j] - tau, 0.f);
    }
    __syncthreads();

    // ---- weight -> gmem ----
    {
        float2* wg = (float2*)(weight + (size_t)blockIdx.x * 8192);
        const float* sc = (const float*)(smp + SCOR);
#pragma unroll
        for (int it = 0; it < 8; ++it) {
            const int idx = t + 512 * it;       // (gi, j)
            const int gi = idx >> 5, j = idx & 31;
            const int g = gi >> 5, i = gi & 31;
            float2 o;
            o.x = sc[(g * 64 + i) * SC_STRIDE + j];
            o.y = sc[(g * 64 + 32 + i) * SC_STRIDE + j];
            wg[idx] = o;
        }
    }

    // ---- phase V: V = X * WV (rows 0..255 of Wbig), staged into STG (T dead) ----
    proj_gemm(smp, sb, 0, (w >> 1) * 32, w & 1, lane, grp, q);
    __syncthreads();

    // ---- phase O: warp (g, dq): O_g[32 x 32] = (0.5*w) * V, both heads in K ----
    {
        const int g = w >> 2, dq = w & 3;
        const float* sc = (const float*)(smp + SCOR);
        float D[4][2][4];
#pragma unroll
        for (int n = 0; n < 4; ++n)
#pragma unroll
            for (int m = 0; m < 2; ++m)
#pragma unroll
                for (int e = 0; e < 4; ++e) D[n][m][e] = 0.f;

        // B (V^T gather) via ldmatrix.trans: matrices (nt, j-octet)
        const unsigned offOB = (unsigned)((g * 32 + (mi & 1) * 8 + lr) * 512
                                          + (mi >> 1) * 16 + dq * 64);

#pragma unroll
        for (int kt = 0; kt < 4; ++kt) {
            const int h = kt >> 1;
            const int jj = (kt * 16 + 2 * q) & 31;
            unsigned Ah[2][4], Al[2][4];
#pragma unroll
            for (int m = 0; m < 2; ++m) {
                const int p0 = g * 64 + h * 32 + m * 16 + grp;
                const float2 f0 = *(const float2*)&sc[p0 * SC_STRIDE + jj];
                const float2 f1 = *(const float2*)&sc[(p0 + 8) * SC_STRIDE + jj];
                const float2 f2 = *(const float2*)&sc[p0 * SC_STRIDE + jj + 8];
                const float2 f3 = *(const float2*)&sc[(p0 + 8) * SC_STRIDE + jj + 8];
                split2(0.5f * f0.x, 0.5f * f0.y, Ah[m][0], Al[m][0]);
                split2(0.5f * f1.x, 0.5f * f1.y, Ah[m][1], Al[m][1]);
                split2(0.5f * f2.x, 0.5f * f2.y, Ah[m][2], Al[m][2]);
                split2(0.5f * f3.x, 0.5f * f3.y, Ah[m][3], Al[m][3]);
            }
            const unsigned koff = (unsigned)((kt & 1) * 8192 + (kt >> 1) * 256);
            unsigned Bh[4][2], Bl[4][2];
            ldmx4t(sb + STGH + ((offOB + koff) ^ xsw),      Bh[0][0], Bh[0][1], Bh[1][0], Bh[1][1]);
            ldmx4t(sb + STGH + ((offOB + koff + 32) ^ xsw), Bh[2][0], Bh[2][1], Bh[3][0], Bh[3][1]);
            ldmx4t(sb + STGL + ((offOB + koff) ^ xsw),      Bl[0][0], Bl[0][1], Bl[1][0], Bl[1][1]);
            ldmx4t(sb + STGL + ((offOB + koff + 32) ^ xsw), Bl[2][0], Bl[2][1], Bl[3][0], Bl[3][1]);
#pragma unroll
            for (int n = 0; n < 4; ++n)
#pragma unroll
                for (int m = 0; m < 2; ++m) {
                    mma_bf(D[n][m], Ah[m], Bh[n]);
                    mma_bf(D[n][m], Al[m], Bh[n]);
                    mma_bf(D[n][m], Ah[m], Bl[n]);
                }
        }
        // out write
#pragma unroll
        for (int n = 0; n < 4; ++n)
#pragma unroll
            for (int m = 0; m < 2; ++m) {
                const int i = m * 16 + grp;
                const int d = dq * 32 + n * 8 + 2 * q;
                const size_t row = ((size_t)blockIdx.x * 4 + g) * 32 + i;
                float2 v0; v0.x = D[n][m][0]; v0.y = D[n][m][1];
                float2 v1; v1.x = D[n][m][2]; v1.y = D[n][m][3];
                *(float2*)&out[row * 128 + d] = v0;
                *(float2*)&out[(row + 8) * 128 + d] = v1;
            }
    }
}

extern "C" void kernel_launch(void* const* d_in, const int* in_sizes, int n_in,
                              void* d_out, int out_size)
{
    (void)in_sizes; (void)n_in; (void)out_size;
    const float* x  = (const float*)d_in[0];
    const float* WK = (const float*)d_in[1];
    const float* WV = (const float*)d_in[2];
    const float* WQ = (const float*)d_in[3];

    float* out    = (float*)d_out;
    float* weight = out + (size_t)4096 * 32 * 128;

    prep_w<<<512, 128>>>(WQ, WK, WV);

    cudaFuncSetAttribute(attn_hmma, cudaFuncAttributeMaxDynamicSharedMemorySize, SMEM_BYTES);
    attn_hmma<<<NBLK, THREADS, SMEM_BYTES>>>(x, out, weight);
}

// round 14
// speedup vs baseline: 1.4644x; 1.2934x over previous
#include <cuda_runtime.h>
#include <cuda_bf16.h>

#define THREADS 512
#define NBLK 1024

// ---- smem byte offsets ----
#define XHI 0u            // X hi  [128][128] bf16, rowbytes 256, swizzled   (32KB); later W-bf16 hi [256][32]
#define XLO 32768u        // X lo                                            (32KB); later W-bf16 lo
#define STGH 65536u       // stage hi [128][256] bf16, rowbytes 512, swz     (64KB)  T then V
#define STGL 131072u      // stage lo                                        (64KB)
#define SCOR 196608u      // scores/weights fp32 [256][34]                   (34816B)
#define SMEM_BYTES 231424u
#define SC_STRIDE 34

// packed W fragments: [octet o (0..63)][kt (0..7)][lane (0..31)] -> uint4 {bh0,bh1,bl0,bl1}
// octet o covers rows n = o*8..o*8+7 of Wbig^T (n<256: WV col n; n>=256: A_h rows)
__device__ __align__(16) unsigned short g_wpk[64 * 8 * 32 * 8];

// ================= prep kernel =================
__global__ void prep_w(const float* __restrict__ WQ, const float* __restrict__ WK,
                       const float* __restrict__ WV)
{
    const int n = blockIdx.x, k1 = threadIdx.x;
    __shared__ float wk[128];
    float val;
    if (n < 256) {
        val = WV[k1 * 256 + n];
    } else {
        const int h = (n - 256) >> 7, k2 = (n - 256) & 127;
        wk[k1] = WK[k2 * 256 + h * 128 + k1];
        __syncthreads();
        const float* wq = WQ + k1 * 256 + h * 128;
        float acc = 0.f;
#pragma unroll 8
        for (int e = 0; e < 128; ++e) acc = fmaf(wq[e], wk[e], acc);
        val = acc * 0.0625f;       // fold 1/sqrt(D*H)
    }
    __nv_bfloat16 hi = __float2bfloat16(val);
    __nv_bfloat16 lo = __float2bfloat16(val - __bfloat162float(hi));

    const int o = n >> 3, grp = n & 7;
    const int kt = k1 >> 4, rem = k1 & 15;
    const int half = rem >> 3, q = (rem & 7) >> 1, parity = rem & 1;
    const int lane = grp * 4 + q;
    const size_t base = ((size_t)((o * 8 + kt) * 32) + lane) * 8;
    g_wpk[base + half * 2 + parity]     = __bfloat16_as_ushort(hi);
    g_wpk[base + 4 + half * 2 + parity] = __bfloat16_as_ushort(lo);
}

// ================= helpers =================
__device__ __forceinline__ unsigned swz(int r, unsigned off) {
    return off ^ (((unsigned)r & 7u) << 4);
}
__device__ __forceinline__ void stsm(unsigned char* smp, unsigned base, int r, int c, int rb, unsigned v) {
    *(unsigned*)(smp + base + swz(r, (unsigned)(r * rb + c * 2))) = v;
}
__device__ __forceinline__ void split2(float a, float b, unsigned& hi, unsigned& lo) {
    __nv_bfloat16 ha = __float2bfloat16(a), hb = __float2bfloat16(b);
    float la = a - __bfloat162float(ha), lb = b - __bfloat162float(hb);
    __nv_bfloat16 lA = __float2bfloat16(la), lB = __float2bfloat16(lb);
    hi = ((unsigned)__bfloat16_as_ushort(hb) << 16) | (unsigned)__bfloat16_as_ushort(ha);
    lo = ((unsigned)__bfloat16_as_ushort(lB) << 16) | (unsigned)__bfloat16_as_ushort(lA);
}
__device__ __forceinline__ void mma_bf(float* d, const unsigned* a, const unsigned* b) {
    asm volatile(
        "mma.sync.aligned.m16n8k16.row.col.f32.bf16.bf16.f32 "
        "{%0,%1,%2,%3}, {%4,%5,%6,%7}, {%8,%9}, {%0,%1,%2,%3};\n"
        : "+f"(d[0]), "+f"(d[1]), "+f"(d[2]), "+f"(d[3])
        : "r"(a[0]), "r"(a[1]), "r"(a[2]), "r"(a[3]), "r"(b[0]), "r"(b[1]));
}
__device__ __forceinline__ void ldmx4(unsigned a, unsigned& r0, unsigned& r1,
                                      unsigned& r2, unsigned& r3) {
    asm volatile("ldmatrix.sync.aligned.m8n8.x4.shared.b16 {%0,%1,%2,%3}, [%4];"
                 : "=r"(r0), "=r"(r1), "=r"(r2), "=r"(r3) : "r"(a));
}
__device__ __forceinline__ void ldmx4t(unsigned a, unsigned& r0, unsigned& r1,
                                       unsigned& r2, unsigned& r3) {
    asm volatile("ldmatrix.sync.aligned.m8n8.x4.trans.shared.b16 {%0,%1,%2,%3}, [%4];"
                 : "=r"(r0), "=r"(r1), "=r"(r2), "=r"(r3) : "r"(a));
}

// projection GEMM: warp computes rows [mh*64, mh*64+64) x cols [nb, nb+32) of
// Y = X(128x128) * Wbig(128x512) slice; 3-pass compensated bf16; stage to STG.
// A (X) fragments loaded once per kt, reused across all 4 n-octets.
// W fragments come from g_wpk as one coalesced LDG.128 per (p, kt).
__device__ __forceinline__ void proj_gemm(unsigned char* smp, unsigned sb,
                                          int nsel, int nb, int mh,
                                          int lane, int grp, int q)
{
    const int mi = lane >> 3, lr = lane & 7;
    const unsigned xsw = (unsigned)lr << 4;
    unsigned offA[4];
#pragma unroll
    for (int m = 0; m < 4; ++m)
        offA[m] = (unsigned)((mh * 64 + m * 16 + (mi & 1) * 8 + lr) * 256 + (mi >> 1) * 16);

    float D[4][4][4];   // [p = octet][m][4]
#pragma unroll
    for (int p = 0; p < 4; ++p)
#pragma unroll
        for (int m = 0; m < 4; ++m)
#pragma unroll
            for (int e = 0; e < 4; ++e) D[p][m][e] = 0.f;

    const uint4* wp = (const uint4*)g_wpk;
    const int ob = (nsel + nb) >> 3;
    unsigned wbase[4];
#pragma unroll
    for (int p = 0; p < 4; ++p)
        wbase[p] = (unsigned)((ob + (p >> 1) * 2 + (p & 1)) * 256 + lane);

#pragma unroll
    for (int kt = 0; kt < 8; ++kt) {
        unsigned bh[4][2], bl[4][2];
#pragma unroll
        for (int p = 0; p < 4; ++p) {
            const uint4 v = wp[wbase[p] + kt * 32];
            bh[p][0] = v.x; bh[p][1] = v.y;
            bl[p][0] = v.z; bl[p][1] = v.w;
        }
        const unsigned ck = (unsigned)(kt * 32);
        unsigned A[4][4];
#pragma unroll
        for (int m = 0; m < 4; ++m)
            ldmx4(sb + XHI + ((offA[m] + ck) ^ xsw), A[m][0], A[m][1], A[m][2], A[m][3]);
#pragma unroll
        for (int p = 0; p < 4; ++p)
#pragma unroll
            for (int m = 0; m < 4; ++m) mma_bf(D[p][m], A[m], bh[p]);
#pragma unroll
        for (int p = 0; p < 4; ++p)
#pragma unroll
            for (int m = 0; m < 4; ++m) mma_bf(D[p][m], A[m], bl[p]);
        // reload A with XLO in the same registers
#pragma unroll
        for (int m = 0; m < 4; ++m)
            ldmx4(sb + XLO + ((offA[m] + ck) ^ xsw), A[m][0], A[m][1], A[m][2], A[m][3]);
#pragma unroll
        for (int p = 0; p < 4; ++p)
#pragma unroll
            for (int m = 0; m < 4; ++m) mma_bf(D[p][m], A[m], bh[p]);
    }

    // stage (split hi/lo)
#pragma unroll
    for (int p = 0; p < 4; ++p)
#pragma unroll
        for (int m = 0; m < 4; ++m) {
            const int r0 = mh * 64 + m * 16 + grp;
            const int c = nb + (p >> 1) * 16 + (p & 1) * 8 + 2 * q;
            unsigned hi, lo;
            split2(D[p][m][0], D[p][m][1], hi, lo);
            stsm(smp, STGH, r0, c, 512, hi);
            stsm(smp, STGL, r0, c, 512, lo);
            split2(D[p][m][2], D[p][m][3], hi, lo);
            stsm(smp, STGH, r0 + 8, c, 512, hi);
            stsm(smp, STGL, r0 + 8, c, 512, lo);
        }
}

// ================= main kernel: 1 CTA = 4 graphs, 16 warps =================
__global__ __launch_bounds__(THREADS, 1)
void attn_hmma(const float* __restrict__ x,
               float* __restrict__ out,      // [B*N, 128]
               float* __restrict__ weight)   // [B*N, 32, 2]
{
    extern __shared__ unsigned char smp[];
    const unsigned sb = (unsigned)__cvta_generic_to_shared(smp);
    const int t = threadIdx.x;
    const int w = t >> 5, lane = t & 31, grp = lane >> 2, q = lane & 3;
    const int mi = lane >> 3, lr = lane & 7;
    const unsigned xsw = (unsigned)lr << 4;

    // ---- load X, split hi/lo ----
    {
        const float2* xg = (const float2*)(x + (size_t)blockIdx.x * 16384);
#pragma unroll
        for (int it = 0; it < 16; ++it) {
            const int e2 = t + 512 * it;
            const float2 v = xg[e2];
            const int r = e2 >> 6, c = (e2 & 63) * 2;
            unsigned hi, lo;
            split2(v.x, v.y, hi, lo);
            stsm(smp, XHI, r, c, 256, hi);
            stsm(smp, XLO, r, c, 256, lo);
        }
    }
    __syncthreads();

    // ---- phase T: T = X * A_h^T (octets 32..63), staged [128][256] (h,k2) ----
    proj_gemm(smp, sb, 256, (w >> 1) * 32, w & 1, lane, grp, q);
    __syncthreads();

    // ---- phase S: warp (g, h, ih): 16 i-rows of S_gh[32x32] = T_gh * X_g^T ----
    {
        const int g = w >> 2, h = (w >> 1) & 1, ih = w & 1;
        float D[4][4];
#pragma unroll
        for (int nt = 0; nt < 4; ++nt)
#pragma unroll
            for (int e = 0; e < 4; ++e) D[nt][e] = 0.f;

        const unsigned offSA = (unsigned)((g * 32 + ih * 16 + (mi & 1) * 8 + lr) * 512
                                          + (mi >> 1) * 16 + h * 256);
        const unsigned offSB = (unsigned)((g * 32 + (mi >> 1) * 8 + lr) * 256 + (mi & 1) * 16);

#pragma unroll
        for (int kt = 0; kt < 8; ++kt) {
            const unsigned ck = (unsigned)(kt * 32);
            unsigned Ah[4], Al[4];
            ldmx4(sb + STGH + ((offSA + ck) ^ xsw), Ah[0], Ah[1], Ah[2], Ah[3]);
            ldmx4(sb + STGL + ((offSA + ck) ^ xsw), Al[0], Al[1], Al[2], Al[3]);
            unsigned Bh[4][2], Bl[4][2];
            ldmx4(sb + XHI + ((offSB + ck) ^ xsw),        Bh[0][0], Bh[0][1], Bh[1][0], Bh[1][1]);
            ldmx4(sb + XHI + ((offSB + 4096 + ck) ^ xsw), Bh[2][0], Bh[2][1], Bh[3][0], Bh[3][1]);
            ldmx4(sb + XLO + ((offSB + ck) ^ xsw),        Bl[0][0], Bl[0][1], Bl[1][0], Bl[1][1]);
            ldmx4(sb + XLO + ((offSB + 4096 + ck) ^ xsw), Bl[2][0], Bl[2][1], Bl[3][0], Bl[3][1]);
#pragma unroll
            for (int nt = 0; nt < 4; ++nt) {
                mma_bf(D[nt], Ah, Bh[nt]);
                mma_bf(D[nt], Al, Bh[nt]);
                mma_bf(D[nt], Ah, Bl[nt]);
            }
        }
        // stage scores fp32
        float* sc = (float*)(smp + SCOR);
#pragma unroll
        for (int nt = 0; nt < 4; ++nt) {
            const int p = g * 64 + h * 32 + ih * 16 + grp;
            const int j = nt * 8 + 2 * q;
            float2 v0; v0.x = D[nt][0]; v0.y = D[nt][1];
            float2 v1; v1.x = D[nt][2]; v1.y = D[nt][3];
            *(float2*)&sc[p * SC_STRIDE + j] = v0;
            *(float2*)&sc[(p + 8) * SC_STRIDE + j] = v1;
        }
    }
    __syncthreads();

    // ---- sparsemax: thread t<256 owns problem p = t (g,h,i); in-place ----
    if (t < 256) {
        float* zrow = (float*)(smp + SCOR) + t * SC_STRIDE;
        float z[32], s[32];
#pragma unroll
        for (int j = 0; j < 32; ++j) { z[j] = zrow[j]; s[j] = z[j]; }
#pragma unroll
        for (int pass = 0; pass < 32; ++pass) {
            const int st = pass & 1;
#pragma unroll
            for (int idx = 0; idx < 31; ++idx) {
                if ((idx & 1) == st) {
                    const float a = s[idx], b = s[idx + 1];
                    s[idx] = fmaxf(a, b); s[idx + 1] = fminf(a, b);
                }
            }
        }
        float csum = 0.f, ssum = 0.f; int ksup = 0;
#pragma unroll
        for (int kk = 1; kk <= 32; ++kk) {
            const float zk = s[kk - 1];
            csum += zk;
            if (1.0f + (float)kk * zk > csum) { ksup += 1; ssum += zk; }
        }
        const float tau = (ssum - 1.0f) / (float)ksup;
#pragma unroll
        for (int j = 0; j < 32; ++j) zrow[j] = fmaxf(z[j] - tau, 0.f);
    }
    __syncthreads();

    // ---- weight -> gmem ----
    {
        float2* wg = (float2*)(weight + (size_t)blockIdx.x * 8192);
        const float* sc = (const float*)(smp + SCOR);
#pragma unroll
        for (int it = 0; it < 8; ++it) {
            const int idx = t + 512 * it;       // (gi, j)
            const int gi = idx >> 5, j = idx & 31;
            const int g = gi >> 5, i = gi & 31;
            float2 o;
            o.x = sc[(g * 64 + i) * SC_STRIDE + j];
            o.y = sc[(g * 64 + 32 + i) * SC_STRIDE + j];
            wg[idx] = o;
        }
    }

    // ---- phase V: V = X * WV (octets 0..31), staged into STG (T dead) ----
    proj_gemm(smp, sb, 0, (w >> 1) * 32, w & 1, lane, grp, q);
    __syncthreads();

    // ---- convert sparsemax weights (0.5-folded) to bf16 hi/lo into X region ----
    // layout: [256 rows p][32 cols j], rowbytes 64, chunk-XOR swizzle (conflict-free ldmatrix)
    {
        const float* sc = (const float*)(smp + SCOR);
        const int p = t >> 1, jh = (t & 1) * 16;
        const unsigned rsw = (((unsigned)p >> 1) & 3u) << 4;
        const unsigned rbase = (unsigned)(p * 64);
#pragma unroll
        for (int jj = 0; jj < 16; jj += 2) {
            const int j = jh + jj;
            const float2 f = *(const float2*)&sc[p * SC_STRIDE + j];
            unsigned hi, lo;
            split2(0.5f * f.x, 0.5f * f.y, hi, lo);
            const unsigned off = rbase + ((((unsigned)j >> 3) << 4) ^ rsw) + (unsigned)((j & 7) * 2);
            *(unsigned*)(smp + XHI + off) = hi;
            *(unsigned*)(smp + XLO + off) = lo;
        }
    }
    __syncthreads();

    // ---- phase O: warp (g, dq): O_g[32 x 32] = (0.5*w) * V, both heads in K ----
    {
        const int g = w >> 2, dq = w & 3;
        float D[4][2][4];
#pragma unroll
        for (int n = 0; n < 4; ++n)
#pragma unroll
            for (int m = 0; m < 2; ++m)
#pragma unroll
                for (int e = 0; e < 4; ++e) D[n][m][e] = 0.f;

        const unsigned offOB = (unsigned)((g * 32 + (mi & 1) * 8 + lr) * 512
                                          + (mi >> 1) * 16 + dq * 64);

#pragma unroll
        for (int kt = 0; kt < 4; ++kt) {
            const int h = kt >> 1, jb = (kt & 1) * 16;
            unsigned Ah[2][4], Al[2][4];
#pragma unroll
            for (int m = 0; m < 2; ++m) {
                const int prow = g * 64 + h * 32 + m * 16 + (mi & 1) * 8 + lr;
                const int cch = (jb >> 3) + (mi >> 1);
                const unsigned aoff = (unsigned)(prow * 64)
                    + (((unsigned)(cch ^ ((prow >> 1) & 3))) << 4);
                ldmx4(sb + XHI + aoff, Ah[m][0], Ah[m][1], Ah[m][2], Ah[m][3]);
                ldmx4(sb + XLO + aoff, Al[m][0], Al[m][1], Al[m][2], Al[m][3]);
            }
            const unsigned koff = (unsigned)((kt & 1) * 8192 + (kt >> 1) * 256);
            unsigned Bh[4][2], Bl[4][2];
            ldmx4t(sb + STGH + ((offOB + koff) ^ xsw),      Bh[0][0], Bh[0][1], Bh[1][0], Bh[1][1]);
            ldmx4t(sb + STGH + ((offOB + koff + 32) ^ xsw), Bh[2][0], Bh[2][1], Bh[3][0], Bh[3][1]);
            ldmx4t(sb + STGL + ((offOB + koff) ^ xsw),      Bl[0][0], Bl[0][1], Bl[1][0], Bl[1][1]);
            ldmx4t(sb + STGL + ((offOB + koff + 32) ^ xsw), Bl[2][0], Bl[2][1], Bl[3][0], Bl[3][1]);
#pragma unroll
            for (int n = 0; n < 4; ++n)
#pragma unroll
                for (int m = 0; m < 2; ++m) {
                    mma_bf(D[n][m], Ah[m], Bh[n]);
                    mma_bf(D[n][m], Al[m], Bh[n]);
                    mma_bf(D[n][m], Ah[m], Bl[n]);
                }
        }
        // out write
#pragma unroll
        for (int n = 0; n < 4; ++n)
#pragma unroll
            for (int m = 0; m < 2; ++m) {
                const int i = m * 16 + grp;
                const int d = dq * 32 + n * 8 + 2 * q;
                const size_t row = ((size_t)blockIdx.x * 4 + g) * 32 + i;
                float2 v0; v0.x = D[n][m][0]; v0.y = D[n][m][1];
                float2 v1; v1.x = D[n][m][2]; v1.y = D[n][m][3];
                *(float2*)&out[row * 128 + d] = v0;
                *(float2*)&out[(row + 8) * 128 + d] = v1;
            }
    }
}

extern "C" void kernel_launch(void* const* d_in, const int* in_sizes, int n_in,
                              void* d_out, int out_size)
{
    (void)in_sizes; (void)n_in; (void)out_size;
    const float* x  = (const float*)d_in[0];
    const float* WK = (const float*)d_in[1];
    const float* WV = (const float*)d_in[2];
    const float* WQ = (const float*)d_in[3];

    float* out    = (float*)d_out;
    float* weight = out + (size_t)4096 * 32 * 128;

    prep_w<<<512, 128>>>(WQ, WK, WV);

    cudaFuncSetAttribute(attn_hmma, cudaFuncAttributeMaxDynamicSharedMemorySize, SMEM_BYTES);
    attn_hmma<<<NBLK, THREADS, SMEM_BYTES>>>(x, out, weight);
}